// round 16
// baseline (speedup 1.0000x reference)
#include <cuda_runtime.h>
#include <math_constants.h>
#include <mma.h>
#include <cuda_fp16.h>
#include <cstdint>

using namespace nvcuda;

#define BATCH 8
#define NPTS  4096
#define KNN   20
#define CIN   26
#define C1    64
#define C2    64
#define C3    128
#define C4    256
#define CCAT  512
#define EMB   512

__device__ __half g_cat[(size_t)BATCH * NPTS * CCAT];   // 32 MB
__device__ __half g_w2h[C2 * C2];
__device__ __half g_w3h[C3 * C2];
__device__ __half g_w4h[C4 * C3];
__device__ __half g_w5h[EMB * CCAT];

// ===================== Kernel 0: all weights fp32 -> half =====================
#define W2N (C2 * C2)
#define W3N (C3 * C2)
#define W4N (C4 * C3)
#define W5N (EMB * CCAT)
__global__ __launch_bounds__(256) void wconv_all(
    const float* __restrict__ w2, const float* __restrict__ w3,
    const float* __restrict__ w4, const float* __restrict__ w5) {
    int i = (blockIdx.x * 256 + threadIdx.x) * 4;
    const float* src; __half* dst; int off;
    if (i < W2N)                  { src = w2; dst = g_w2h; off = 0; }
    else if (i < W2N + W3N)       { src = w3; dst = g_w3h; off = W2N; }
    else if (i < W2N + W3N + W4N) { src = w4; dst = g_w4h; off = W2N + W3N; }
    else                          { src = w5; dst = g_w5h; off = W2N + W3N + W4N; }
    int j = i - off;
    float4 v = *(const float4*)(src + j);
    *(half2*)(dst + j)     = __floats2half2_rn(v.x, v.y);
    *(half2*)(dst + j + 2) = __floats2half2_rn(v.z, v.w);
}

// ===================== Fused kernel: KNN (warp-coop) + L1..L4 (wmma fp16) =====================
// Block = 8 points, 256 threads (8 warps; warp w owns point w).
// Dyn smem union: phase A = xs[4096] float4 (64KB); phase B = hb/h2b/wb0/wb1 (103.4KB).
#define LPTS 8
#define LROWS (LPTS * KNN)   // 160
#define HBLD 136
#define H2LD2 72
#define WBH 9216
#define DYNH (LROWS * HBLD + LROWS * H2LD2 + 2 * WBH)   // 51712 halves = 103424 B

typedef wmma::fragment<wmma::matrix_a, 16, 16, 16, half, wmma::row_major> HA;
typedef wmma::fragment<wmma::matrix_b, 16, 16, 16, half, wmma::col_major> HB;
typedef wmma::fragment<wmma::accumulator, 16, 16, 16, float> HCf;
typedef wmma::fragment<wmma::accumulator, 16, 16, 16, half>  HCh;

__device__ __forceinline__ void store_relu_half(half* dst, int ld, HCf& cf) {
    HCh ch;
#pragma unroll
    for (int i = 0; i < cf.num_elements; ++i)
        ch.x[i] = __float2half_rn(fmaxf(cf.x[i], 0.f));
    wmma::store_matrix_sync(dst, ch, ld, wmma::mem_row_major);
}

__global__ __launch_bounds__(256, 2) void fused_kernel(
    const float* __restrict__ x, const float* __restrict__ w1) {
    extern __shared__ half hsm[];
    float4* xs = (float4*)hsm;       // phase A: 4096 * 16B, aliases hb+front of h2b
    half* hb  = hsm;                 // 160*136
    half* h2b = hb + LROWS * HBLD;   // 160*72
    half* wb0 = h2b + LROWS * H2LD2; // beyond 64KB: NOT aliased by xs
    half* wb1 = wb0 + WBH;
    __shared__ float W1t[CIN * C1];
    __shared__ float s_nbr[LPTS][KNN][3];
    __shared__ float s_dist[LPTS][KNN];
    __shared__ float s_xn[LPTS][3];

    const int tid = threadIdx.x, warp = tid >> 5, lane = tid & 31;
    const size_t pt0 = (size_t)blockIdx.x * LPTS;
    const int b = (int)(pt0 >> 12);
    const float* xb = x + (size_t)b * 3 * NPTS;

    // ---- phase A stage: W1t, W2->wb0 (no alias), xs ----
    for (int i = tid; i < CIN * C1; i += 256) { int o = i / CIN, c = i % CIN; W1t[c * C1 + o] = w1[i]; }
    {
        const uint4* s = (const uint4*)g_w2h;
#pragma unroll
        for (int i = tid; i < 512; i += 256) { int o = i >> 3, q = i & 7; *(uint4*)(wb0 + o * H2LD2 + q * 8) = s[i]; }
    }
    for (int m = tid; m < NPTS; m += 256) {
        float x0 = xb[m], x1 = xb[NPTS + m], x2 = xb[2 * NPTS + m];
        xs[m] = make_float4(x0, x1, x2, fmaf(x0, x0, fmaf(x1, x1, x2 * x2)));
    }
    __syncthreads();

    // ---- KNN: warp w -> point n0+w (warp-cooperative, in registers) ----
    const int n = (int)(pt0 & (NPTS - 1)) + warp;
    float4 p = xs[n];
    {
        const float a0 = -2.f * p.x, a1 = -2.f * p.y, a2 = -2.f * p.z;
        float bv = CUDART_INF_F;  int bi = 0x7FFFFFFF;
        float t19 = CUDART_INF_F; int ti19 = 0x7FFFFFFF;
        for (int it = 0; it < NPTS / 32; ++it) {
            const int m = it * 32 + lane;
            float4 q = xs[m];
            float v = fmaf(a0, q.x, fmaf(a1, q.y, fmaf(a2, q.z, q.w)));
            unsigned processed = 0;
            while (true) {
                bool qf = (v < t19) || (v == t19 && m < ti19);
                unsigned mask = __ballot_sync(0xffffffffu, qf) & ~processed;
                if (!mask) break;
                int src = __ffs(mask) - 1;
                processed |= (1u << src);
                float vv = __shfl_sync(0xffffffffu, v, src);
                int   ii = __shfl_sync(0xffffffffu, m, src);
                bool pr = (vv < bv) || (vv == bv && ii < bi);
                unsigned pm = __ballot_sync(0xffffffffu, pr);
                int pos = __ffs(pm) - 1;
                float uv = __shfl_up_sync(0xffffffffu, bv, 1);
                int   ui = __shfl_up_sync(0xffffffffu, bi, 1);
                if (pr) { bv = (lane == pos) ? vv : uv; bi = (lane == pos) ? ii : ui; }
                t19  = __shfl_sync(0xffffffffu, bv, 19);
                ti19 = __shfl_sync(0xffffffffu, bi, 19);
            }
        }
        // gather from xs (reads only; still phase A)
        if (lane < KNN) {
            float4 q = xs[bi];
            s_nbr[warp][lane][0] = q.x; s_nbr[warp][lane][1] = q.y; s_nbr[warp][lane][2] = q.z;
            float d0 = q.x - p.x, d1 = q.y - p.y, d2 = q.z - p.z;
            s_dist[warp][lane] = sqrtf(fmaf(d0, d0, fmaf(d1, d1, d2 * d2)) + 1e-12f);
        }
        if (lane == 0) { s_xn[warp][0] = p.x; s_xn[warp][1] = p.y; s_xn[warp][2] = p.z; }
    }
    __syncthreads();   // all xs reads done; hb/h2b may now be written

    // ---- L1 scalar -> hb, x1 -> cat[0:64] ----
    {
        int o = tid & 63;
#pragma unroll
        for (int pi = 0; pi < 2; ++pi) {
            int pp = (tid >> 6) + pi * 4;
            float base = 0.f;
#pragma unroll
            for (int d = 0; d < 3; ++d) base = fmaf(W1t[d * C1 + o], s_xn[pp][d], base);
#pragma unroll
            for (int j = 0; j < KNN; ++j) base = fmaf(W1t[(6 + j) * C1 + o], s_dist[pp][j], base);
            float wa = W1t[3 * C1 + o], wb = W1t[4 * C1 + o], wc = W1t[5 * C1 + o];
            float mx = 0.f;
#pragma unroll
            for (int k = 0; k < KNN; ++k) {
                float v = fmaf(wa, s_nbr[pp][k][0], fmaf(wb, s_nbr[pp][k][1], fmaf(wc, s_nbr[pp][k][2], base)));
                v = fmaxf(v, 0.f);
                mx = fmaxf(mx, v);
                hb[(pp * KNN + k) * HBLD + o] = __float2half_rn(v);
            }
            g_cat[(pt0 + pp) * CCAT + o] = __float2half_rn(mx);
        }
    }
    __syncthreads();

    // ---- L2 MMA (wb0), prefetch W3 -> wb1 ----
    {
        uint4 pw[4];
        const uint4* s3 = (const uint4*)g_w3h;
#pragma unroll
        for (int i = 0; i < 4; ++i) pw[i] = s3[tid + i * 256];

        const int nt = warp & 3, hf = warp >> 2;
        HA fa; HB fb; HCf fc[5];
#pragma unroll
        for (int i = 0; i < 5; ++i) wmma::fill_fragment(fc[i], 0.f);
#pragma unroll
        for (int kt = 0; kt < 4; ++kt) {
            wmma::load_matrix_sync(fb, wb0 + nt * 16 * H2LD2 + kt * 16, H2LD2);
#pragma unroll
            for (int i = 0; i < 5; ++i) {
                wmma::load_matrix_sync(fa, hb + (hf * 5 + i) * 16 * HBLD + kt * 16, HBLD);
                wmma::mma_sync(fc[i], fa, fb, fc[i]);
            }
        }
#pragma unroll
        for (int i = 0; i < 5; ++i)
            store_relu_half(h2b + (hf * 5 + i) * 16 * H2LD2 + nt * 16, H2LD2, fc[i]);

#pragma unroll
        for (int i = 0; i < 4; ++i) {
            int lin = tid + i * 256, o = lin >> 3, q = lin & 7;
            *(uint4*)(wb1 + o * H2LD2 + q * 8) = pw[i];
        }
    }
    __syncthreads();

    // ---- x2 epi + L3 MMA (wb1), prefetch W4c0 -> wb0 ----
    {
        uint4 pw[4];
        const uint4* s4 = (const uint4*)g_w4h;
#pragma unroll
        for (int i = 0; i < 4; ++i) pw[i] = s4[tid + i * 256];

        {
            int pp = tid >> 5, c = tid & 31;
            half2 mx = __floats2half2_rn(0.f, 0.f);
#pragma unroll
            for (int k = 0; k < KNN; ++k)
                mx = __hmax2(mx, *(half2*)(h2b + (pp * KNN + k) * H2LD2 + 2 * c));
            *(half2*)(&g_cat[(pt0 + pp) * CCAT + 64 + 2 * c]) = mx;
        }

        HA fa; HB fb;
#pragma unroll
        for (int pass = 0; pass < 2; ++pass) {
            HCf fc[5];
#pragma unroll
            for (int i = 0; i < 5; ++i) wmma::fill_fragment(fc[i], 0.f);
#pragma unroll
            for (int kt = 0; kt < 4; ++kt) {
                wmma::load_matrix_sync(fb, wb1 + warp * 16 * H2LD2 + kt * 16, H2LD2);
#pragma unroll
                for (int i = 0; i < 5; ++i) {
                    wmma::load_matrix_sync(fa, h2b + (pass * 5 + i) * 16 * H2LD2 + kt * 16, H2LD2);
                    wmma::mma_sync(fc[i], fa, fb, fc[i]);
                }
            }
#pragma unroll
            for (int i = 0; i < 5; ++i)
                store_relu_half(hb + (pass * 5 + i) * 16 * HBLD + warp * 16, HBLD, fc[i]);
        }

#pragma unroll
        for (int i = 0; i < 4; ++i) {
            int lin = tid + i * 256, o = lin >> 4, q = lin & 15;
            *(uint4*)(wb0 + o * HBLD + q * 8) = pw[i];
        }
    }
    __syncthreads();

    // ---- L4 chunks (x3 epi merged into c0; x4 epi per chunk) ----
    for (int co = 0; co < 4; ++co) {
        half* cur = (co & 1) ? wb1 : wb0;
        half* nxt = (co & 1) ? wb0 : wb1;
        uint4 pw[4];
        if (co < 3) {
            const uint4* s4 = (const uint4*)(g_w4h + (size_t)(co + 1) * 64 * 128);
#pragma unroll
            for (int i = 0; i < 4; ++i) pw[i] = s4[tid + i * 256];
        }
        if (co == 0) {
#pragma unroll
            for (int pi = 0; pi < 2; ++pi) {
                int slot = tid + pi * 256;
                int pp = slot >> 6, c = slot & 63;
                half2 mx = __floats2half2_rn(0.f, 0.f);
#pragma unroll
                for (int k = 0; k < KNN; ++k)
                    mx = __hmax2(mx, *(half2*)(hb + (pp * KNN + k) * HBLD + 2 * c));
                *(half2*)(&g_cat[(pt0 + pp) * CCAT + 128 + 2 * c]) = mx;
            }
        }
        {
            const int nt = warp & 3, hf = warp >> 2;
            HA fa; HB fb; HCf fc[5];
#pragma unroll
            for (int i = 0; i < 5; ++i) wmma::fill_fragment(fc[i], 0.f);
#pragma unroll
            for (int kt = 0; kt < 8; ++kt) {
                wmma::load_matrix_sync(fb, cur + nt * 16 * HBLD + kt * 16, HBLD);
#pragma unroll
                for (int i = 0; i < 5; ++i) {
                    wmma::load_matrix_sync(fa, hb + (hf * 5 + i) * 16 * HBLD + kt * 16, HBLD);
                    wmma::mma_sync(fc[i], fa, fb, fc[i]);
                }
            }
#pragma unroll
            for (int i = 0; i < 5; ++i)
                store_relu_half(h2b + (hf * 5 + i) * 16 * H2LD2 + nt * 16, H2LD2, fc[i]);
        }
        if (co < 3) {
#pragma unroll
            for (int i = 0; i < 4; ++i) {
                int lin = tid + i * 256, o = lin >> 4, q = lin & 15;
                *(uint4*)(nxt + o * HBLD + q * 8) = pw[i];
            }
        }
        __syncthreads();
        {
            int pp = tid >> 5, c = tid & 31;
            half2 mx = __floats2half2_rn(0.f, 0.f);
#pragma unroll
            for (int k = 0; k < KNN; ++k)
                mx = __hmax2(mx, *(half2*)(h2b + (pp * KNN + k) * H2LD2 + 2 * c));
            *(half2*)(&g_cat[(pt0 + pp) * CCAT + 256 + co * 64 + 2 * c]) = mx;
        }
        if (co < 3) __syncthreads();
    }
}

// ===================== Kernel: L5 tiled GEMM (wmma fp16) =====================
#define KC5   64
#define ALD5  72
#define TILEH (128 * ALD5)

__global__ __launch_bounds__(256, 2) void l5_kernel(float* __restrict__ out) {
    extern __shared__ half hsm5[];
    half* bufA[2] = { hsm5,         hsm5 + 2 * TILEH };
    half* bufB[2] = { hsm5 + TILEH, hsm5 + 3 * TILEH };

    const int tid = threadIdx.x, warp = tid >> 5;
    const int n0 = blockIdx.x * 128;
    const int o0 = blockIdx.y * 128;
    const int b  = blockIdx.z;
    const half* catg = g_cat + ((size_t)b * NPTS + n0) * CCAT;
    const half* wg   = g_w5h + (size_t)o0 * CCAT;
    const int wr = warp >> 2, wc = warp & 3;

    HCf fc[4][2];
#pragma unroll
    for (int i = 0; i < 4; ++i) { wmma::fill_fragment(fc[i][0], 0.f); wmma::fill_fragment(fc[i][1], 0.f); }

    auto stage = [&](int kc, int bi) {
        half* pa = bufA[bi]; half* pb = bufB[bi];
#pragma unroll
        for (int it = 0; it < 4; ++it) {
            int lin = tid + it * 256;
            int r = lin >> 3, q = lin & 7;
            *(uint4*)(pa + r * ALD5 + q * 8) = *(const uint4*)(wg   + (size_t)r * CCAT + kc * KC5 + q * 8);
            *(uint4*)(pb + r * ALD5 + q * 8) = *(const uint4*)(catg + (size_t)r * CCAT + kc * KC5 + q * 8);
        }
    };

    stage(0, 0);
    __syncthreads();

    HA fa; HB fb;
    for (int kc = 0; kc < 8; ++kc) {
        const int cur = kc & 1;
        if (kc + 1 < 8) stage(kc + 1, cur ^ 1);
        const half* A = bufA[cur];
        const half* B = bufB[cur];
#pragma unroll
        for (int kt = 0; kt < 4; ++kt) {
#pragma unroll
            for (int j = 0; j < 2; ++j) {
                wmma::load_matrix_sync(fb, B + (wc * 32 + j * 16) * ALD5 + kt * 16, ALD5);
#pragma unroll
                for (int i = 0; i < 4; ++i) {
                    wmma::load_matrix_sync(fa, A + (wr * 64 + i * 16) * ALD5 + kt * 16, ALD5);
                    wmma::mma_sync(fc[i][j], fa, fb, fc[i][j]);
                }
            }
        }
        __syncthreads();
    }

    float* scratch = (float*)hsm5;
#pragma unroll
    for (int i = 0; i < 4; ++i)
#pragma unroll
        for (int j = 0; j < 2; ++j)
            wmma::store_matrix_sync(scratch + (wr * 64 + i * 16) * 132 + wc * 32 + j * 16,
                                    fc[i][j], 132, wmma::mem_row_major);
    __syncthreads();

    for (int i = tid; i < 128 * 128; i += 256) {
        int o = i >> 7, n = i & 127;
        out[((size_t)b * EMB + o0 + o) * NPTS + n0 + n] = fmaxf(scratch[o * 132 + n], 0.f);
    }
}

// ===================== launch =====================
extern "C" void kernel_launch(void* const* d_in, const int* in_sizes, int n_in,
                              void* d_out, int out_size) {
    const float* x  = (const float*)d_in[0];
    const float* w1 = (const float*)d_in[1];
    const float* w2 = (const float*)d_in[2];
    const float* w3 = (const float*)d_in[3];
    const float* w4 = (const float*)d_in[4];
    const float* w5 = (const float*)d_in[5];
    float* out = (float*)d_out;

    const int fused_smem = DYNH * sizeof(half);        // 103424 B (>= 64KB xs)
    const int l5_smem    = 4 * TILEH * sizeof(half);   // 73728 B
    cudaFuncSetAttribute(fused_kernel, cudaFuncAttributeMaxDynamicSharedMemorySize, fused_smem);
    cudaFuncSetAttribute(l5_kernel,    cudaFuncAttributeMaxDynamicSharedMemorySize, l5_smem);

    wconv_all<<<(W2N + W3N + W4N + W5N) / 1024, 256>>>(w2, w3, w4, w5);
    fused_kernel<<<(BATCH * NPTS) / LPTS, 256, fused_smem>>>(x, w1);
    l5_kernel<<<dim3(NPTS / 128, EMB / 128, BATCH), 256, l5_smem>>>(out);
}

// round 17
// speedup vs baseline: 1.2462x; 1.2462x over previous
#include <cuda_runtime.h>
#include <math_constants.h>
#include <mma.h>
#include <cuda_fp16.h>
#include <cstdint>

using namespace nvcuda;

#define BATCH 8
#define NPTS  4096
#define KNN   20
#define CIN   26
#define C1    64
#define C2    64
#define C3    128
#define C4    256
#define CCAT  512
#define EMB   512

__device__ int    g_idx[BATCH * NPTS * KNN];
__device__ __half g_cat[(size_t)BATCH * NPTS * CCAT];   // 32 MB
__device__ __half g_w2h[C2 * C2];
__device__ __half g_w3h[C3 * C2];
__device__ __half g_w4h[C4 * C3];
__device__ __half g_w5h[EMB * CCAT];

// ===================== Kernel 0: all weights fp32 -> half =====================
#define W2N (C2 * C2)
#define W3N (C3 * C2)
#define W4N (C4 * C3)
#define W5N (EMB * CCAT)
__global__ __launch_bounds__(256) void wconv_all(
    const float* __restrict__ w2, const float* __restrict__ w3,
    const float* __restrict__ w4, const float* __restrict__ w5) {
    int i = (blockIdx.x * 256 + threadIdx.x) * 4;
    const float* src; __half* dst; int off;
    if (i < W2N)                  { src = w2; dst = g_w2h; off = 0; }
    else if (i < W2N + W3N)       { src = w3; dst = g_w3h; off = W2N; }
    else if (i < W2N + W3N + W4N) { src = w4; dst = g_w4h; off = W2N + W3N; }
    else                          { src = w5; dst = g_w5h; off = W2N + W3N + W4N; }
    int j = i - off;
    float4 v = *(const float4*)(src + j);
    *(half2*)(dst + j)     = __floats2half2_rn(v.x, v.y);
    *(half2*)(dst + j + 2) = __floats2half2_rn(v.z, v.w);
}

// ===================== Kernel 1: exact 20-NN — 1 point per WARP, 2 blocks/SM =====================
__global__ __launch_bounds__(512, 2) void knn_kernel(const float* __restrict__ x) {
    extern __shared__ float4 xs[];
    const int b = blockIdx.y;
    const float* xb = x + (size_t)b * 3 * NPTS;
    for (int m = threadIdx.x; m < NPTS; m += 512) {
        float x0 = xb[m], x1 = xb[NPTS + m], x2 = xb[2 * NPTS + m];
        xs[m] = make_float4(x0, x1, x2, fmaf(x0, x0, fmaf(x1, x1, x2 * x2)));
    }
    __syncthreads();
    const int warp = threadIdx.x >> 5, lane = threadIdx.x & 31;
    const int n = blockIdx.x * 16 + warp;
    float4 p = xs[n];
    const float a0 = -2.f * p.x, a1 = -2.f * p.y, a2 = -2.f * p.z;

    float bv = CUDART_INF_F;  int bi = 0x7FFFFFFF;
    float t19 = CUDART_INF_F; int ti19 = 0x7FFFFFFF;

    for (int it = 0; it < NPTS / 32; ++it) {
        const int m = it * 32 + lane;
        float4 q = xs[m];
        float v = fmaf(a0, q.x, fmaf(a1, q.y, fmaf(a2, q.z, q.w)));
        unsigned processed = 0;
        while (true) {
            bool qf = (v < t19) || (v == t19 && m < ti19);
            unsigned mask = __ballot_sync(0xffffffffu, qf) & ~processed;
            if (!mask) break;
            int src = __ffs(mask) - 1;
            processed |= (1u << src);
            float vv = __shfl_sync(0xffffffffu, v, src);
            int   ii = __shfl_sync(0xffffffffu, m, src);
            bool pr = (vv < bv) || (vv == bv && ii < bi);
            unsigned pm = __ballot_sync(0xffffffffu, pr);
            int pos = __ffs(pm) - 1;
            float uv = __shfl_up_sync(0xffffffffu, bv, 1);
            int   ui = __shfl_up_sync(0xffffffffu, bi, 1);
            if (pr) { bv = (lane == pos) ? vv : uv; bi = (lane == pos) ? ii : ui; }
            t19  = __shfl_sync(0xffffffffu, bv, 19);
            ti19 = __shfl_sync(0xffffffffu, bi, 19);
        }
    }
    if (lane < KNN)
        g_idx[((size_t)b * NPTS + n) * KNN + lane] = bi;
}

// ===================== Kernel 2: fused L1 + L2/L3/L4 (prefetch + merged epilogues) =====================
#define LPTS 8
#define LROWS (LPTS * KNN)   // 160
#define HBLD 136
#define H2LD2 72
#define WBH 9216             // halves per weight buffer

typedef wmma::fragment<wmma::matrix_a, 16, 16, 16, half, wmma::row_major> HA;
typedef wmma::fragment<wmma::matrix_b, 16, 16, 16, half, wmma::col_major> HB;
typedef wmma::fragment<wmma::accumulator, 16, 16, 16, float> HCf;
typedef wmma::fragment<wmma::accumulator, 16, 16, 16, half>  HCh;

__device__ __forceinline__ void store_relu_half(half* dst, int ld, HCf& cf) {
    HCh ch;
#pragma unroll
    for (int i = 0; i < cf.num_elements; ++i)
        ch.x[i] = __float2half_rn(fmaxf(cf.x[i], 0.f));
    wmma::store_matrix_sync(dst, ch, ld, wmma::mem_row_major);
}

__global__ __launch_bounds__(256, 2) void l1234_kernel(
    const float* __restrict__ x, const float* __restrict__ w1) {
    extern __shared__ half hsm[];
    half* hb  = hsm;                 // 160*136 = 21760 (h1, then h3)
    half* h2b = hb + LROWS * HBLD;   // 160*72  = 11520 (h2 / l4-chunk out)
    half* wb0 = h2b + LROWS * H2LD2; // 9216
    half* wb1 = wb0 + WBH;           // 9216
    __shared__ float W1t[CIN * C1];
    __shared__ float s_nbr[LPTS][KNN][3];
    __shared__ float s_dist[LPTS][KNN];
    __shared__ float s_xn[LPTS][3];

    const int tid = threadIdx.x, warp = tid >> 5;
    const size_t pt0 = (size_t)blockIdx.x * LPTS;

    for (int i = tid; i < CIN * C1; i += 256) { int o = i / CIN, c = i % CIN; W1t[c * C1 + o] = w1[i]; }
    {   // W2 -> wb0 (512 uint4)
        const uint4* s = (const uint4*)g_w2h;
#pragma unroll
        for (int i = tid; i < 512; i += 256) { int o = i >> 3, q = i & 7; *(uint4*)(wb0 + o * H2LD2 + q * 8) = s[i]; }
    }

    if (tid < LPTS * KNN) {
        int p = tid / KNN, k = tid % KNN;
        size_t pt = pt0 + p;
        int b = (int)(pt >> 12), n = (int)(pt & (NPTS - 1));
        const float* xb = x + (size_t)b * 3 * NPTS;
        int nb = g_idx[pt * KNN + k];
        float c0 = xb[n], c1 = xb[NPTS + n], c2 = xb[2 * NPTS + n];
        float n0 = xb[nb], n1 = xb[NPTS + nb], n2 = xb[2 * NPTS + nb];
        s_nbr[p][k][0] = n0; s_nbr[p][k][1] = n1; s_nbr[p][k][2] = n2;
        float d0 = n0 - c0, d1 = n1 - c1, d2 = n2 - c2;
        s_dist[p][k] = sqrtf(fmaf(d0, d0, fmaf(d1, d1, d2 * d2)) + 1e-12f);
        if (k < 3) s_xn[p][k] = xb[k * NPTS + n];
    }
    __syncthreads();

    // ---- L1 scalar -> hb, x1 -> cat[0:64] ----
    {
        int o = tid & 63;
#pragma unroll
        for (int pi = 0; pi < 2; ++pi) {
            int p = (tid >> 6) + pi * 4;
            float base = 0.f;
#pragma unroll
            for (int d = 0; d < 3; ++d) base = fmaf(W1t[d * C1 + o], s_xn[p][d], base);
#pragma unroll
            for (int j = 0; j < KNN; ++j) base = fmaf(W1t[(6 + j) * C1 + o], s_dist[p][j], base);
            float wa = W1t[3 * C1 + o], wb = W1t[4 * C1 + o], wc = W1t[5 * C1 + o];
            float mx = 0.f;
#pragma unroll
            for (int k = 0; k < KNN; ++k) {
                float v = fmaf(wa, s_nbr[p][k][0], fmaf(wb, s_nbr[p][k][1], fmaf(wc, s_nbr[p][k][2], base)));
                v = fmaxf(v, 0.f);
                mx = fmaxf(mx, v);
                hb[(p * KNN + k) * HBLD + o] = __float2half_rn(v);
            }
            g_cat[(pt0 + p) * CCAT + o] = __float2half_rn(mx);
        }
    }
    __syncthreads();

    // ---- Phase: L2 MMA (wb0), prefetch W3 -> wb1 ----
    {
        uint4 pw[4];
        const uint4* s3 = (const uint4*)g_w3h;
#pragma unroll
        for (int i = 0; i < 4; ++i) pw[i] = s3[tid + i * 256];

        const int nt = warp & 3, hf = warp >> 2;
        HA fa; HB fb; HCf fc[5];
#pragma unroll
        for (int i = 0; i < 5; ++i) wmma::fill_fragment(fc[i], 0.f);
#pragma unroll
        for (int kt = 0; kt < 4; ++kt) {
            wmma::load_matrix_sync(fb, wb0 + nt * 16 * H2LD2 + kt * 16, H2LD2);
#pragma unroll
            for (int i = 0; i < 5; ++i) {
                wmma::load_matrix_sync(fa, hb + (hf * 5 + i) * 16 * HBLD + kt * 16, HBLD);
                wmma::mma_sync(fc[i], fa, fb, fc[i]);
            }
        }
#pragma unroll
        for (int i = 0; i < 5; ++i)
            store_relu_half(h2b + (hf * 5 + i) * 16 * H2LD2 + nt * 16, H2LD2, fc[i]);

#pragma unroll
        for (int i = 0; i < 4; ++i) {
            int lin = tid + i * 256, o = lin >> 3, q = lin & 7;
            *(uint4*)(wb1 + o * H2LD2 + q * 8) = pw[i];
        }
    }
    __syncthreads();

    // ---- Phase: x2 epi + L3 MMA (wb1), prefetch W4c0 -> wb0 ----
    {
        uint4 pw[4];
        const uint4* s4 = (const uint4*)g_w4h;
#pragma unroll
        for (int i = 0; i < 4; ++i) pw[i] = s4[tid + i * 256];

        {   // x2: 8 pts x 32 half2 cols
            int p = tid >> 5, c = tid & 31;
            half2 mx = __floats2half2_rn(0.f, 0.f);
#pragma unroll
            for (int k = 0; k < KNN; ++k)
                mx = __hmax2(mx, *(half2*)(h2b + (p * KNN + k) * H2LD2 + 2 * c));
            *(half2*)(&g_cat[(pt0 + p) * CCAT + 64 + 2 * c]) = mx;
        }

        HA fa; HB fb;
#pragma unroll
        for (int pass = 0; pass < 2; ++pass) {
            HCf fc[5];
#pragma unroll
            for (int i = 0; i < 5; ++i) wmma::fill_fragment(fc[i], 0.f);
#pragma unroll
            for (int kt = 0; kt < 4; ++kt) {
                wmma::load_matrix_sync(fb, wb1 + warp * 16 * H2LD2 + kt * 16, H2LD2);
#pragma unroll
                for (int i = 0; i < 5; ++i) {
                    wmma::load_matrix_sync(fa, h2b + (pass * 5 + i) * 16 * H2LD2 + kt * 16, H2LD2);
                    wmma::mma_sync(fc[i], fa, fb, fc[i]);
                }
            }
#pragma unroll
            for (int i = 0; i < 5; ++i)
                store_relu_half(hb + (pass * 5 + i) * 16 * HBLD + warp * 16, HBLD, fc[i]);
        }

#pragma unroll
        for (int i = 0; i < 4; ++i) {
            int lin = tid + i * 256, o = lin >> 4, q = lin & 15;
            *(uint4*)(wb0 + o * HBLD + q * 8) = pw[i];
        }
    }
    __syncthreads();

    // ---- L4 chunks (x3 epi merged into c0; x4 epi per chunk) ----
    for (int co = 0; co < 4; ++co) {
        half* cur = (co & 1) ? wb1 : wb0;
        half* nxt = (co & 1) ? wb0 : wb1;
        uint4 pw[4];
        if (co < 3) {
            const uint4* s4 = (const uint4*)(g_w4h + (size_t)(co + 1) * 64 * 128);
#pragma unroll
            for (int i = 0; i < 4; ++i) pw[i] = s4[tid + i * 256];
        }
        if (co == 0) {   // x3 epi: 8 pts x 64 half2 cols
#pragma unroll
            for (int pi = 0; pi < 2; ++pi) {
                int slot = tid + pi * 256;
                int p = slot >> 6, c = slot & 63;
                half2 mx = __floats2half2_rn(0.f, 0.f);
#pragma unroll
                for (int k = 0; k < KNN; ++k)
                    mx = __hmax2(mx, *(half2*)(hb + (p * KNN + k) * HBLD + 2 * c));
                *(half2*)(&g_cat[(pt0 + p) * CCAT + 128 + 2 * c]) = mx;
            }
        }
        {
            const int nt = warp & 3, hf = warp >> 2;
            HA fa; HB fb; HCf fc[5];
#pragma unroll
            for (int i = 0; i < 5; ++i) wmma::fill_fragment(fc[i], 0.f);
#pragma unroll
            for (int kt = 0; kt < 8; ++kt) {
                wmma::load_matrix_sync(fb, cur + nt * 16 * HBLD + kt * 16, HBLD);
#pragma unroll
                for (int i = 0; i < 5; ++i) {
                    wmma::load_matrix_sync(fa, hb + (hf * 5 + i) * 16 * HBLD + kt * 16, HBLD);
                    wmma::mma_sync(fc[i], fa, fb, fc[i]);
                }
            }
#pragma unroll
            for (int i = 0; i < 5; ++i)
                store_relu_half(h2b + (hf * 5 + i) * 16 * H2LD2 + nt * 16, H2LD2, fc[i]);
        }
        if (co < 3) {
#pragma unroll
            for (int i = 0; i < 4; ++i) {
                int lin = tid + i * 256, o = lin >> 4, q = lin & 15;
                *(uint4*)(nxt + o * HBLD + q * 8) = pw[i];
            }
        }
        __syncthreads();
        {   // x4 epi: 8 pts x 32 half2 cols
            int p = tid >> 5, c = tid & 31;
            half2 mx = __floats2half2_rn(0.f, 0.f);
#pragma unroll
            for (int k = 0; k < KNN; ++k)
                mx = __hmax2(mx, *(half2*)(h2b + (p * KNN + k) * H2LD2 + 2 * c));
            *(half2*)(&g_cat[(pt0 + p) * CCAT + 256 + co * 64 + 2 * c]) = mx;
        }
        if (co < 3) __syncthreads();
    }
}

// ===================== Kernel 3: L5 tiled GEMM (wmma fp16) =====================
#define KC5   64
#define ALD5  72
#define TILEH (128 * ALD5)

__global__ __launch_bounds__(256, 2) void l5_kernel(float* __restrict__ out) {
    extern __shared__ half hsm5[];
    half* bufA[2] = { hsm5,         hsm5 + 2 * TILEH };
    half* bufB[2] = { hsm5 + TILEH, hsm5 + 3 * TILEH };

    const int tid = threadIdx.x, warp = tid >> 5;
    const int n0 = blockIdx.x * 128;
    const int o0 = blockIdx.y * 128;
    const int b  = blockIdx.z;
    const half* catg = g_cat + ((size_t)b * NPTS + n0) * CCAT;
    const half* wg   = g_w5h + (size_t)o0 * CCAT;
    const int wr = warp >> 2, wc = warp & 3;

    HCf fc[4][2];
#pragma unroll
    for (int i = 0; i < 4; ++i) { wmma::fill_fragment(fc[i][0], 0.f); wmma::fill_fragment(fc[i][1], 0.f); }

    auto stage = [&](int kc, int bi) {
        half* pa = bufA[bi]; half* pb = bufB[bi];
#pragma unroll
        for (int it = 0; it < 4; ++it) {
            int lin = tid + it * 256;
            int r = lin >> 3, q = lin & 7;
            *(uint4*)(pa + r * ALD5 + q * 8) = *(const uint4*)(wg   + (size_t)r * CCAT + kc * KC5 + q * 8);
            *(uint4*)(pb + r * ALD5 + q * 8) = *(const uint4*)(catg + (size_t)r * CCAT + kc * KC5 + q * 8);
        }
    };

    stage(0, 0);
    __syncthreads();

    HA fa; HB fb;
    for (int kc = 0; kc < 8; ++kc) {
        const int cur = kc & 1;
        if (kc + 1 < 8) stage(kc + 1, cur ^ 1);
        const half* A = bufA[cur];
        const half* B = bufB[cur];
#pragma unroll
        for (int kt = 0; kt < 4; ++kt) {
#pragma unroll
            for (int j = 0; j < 2; ++j) {
                wmma::load_matrix_sync(fb, B + (wc * 32 + j * 16) * ALD5 + kt * 16, ALD5);
#pragma unroll
                for (int i = 0; i < 4; ++i) {
                    wmma::load_matrix_sync(fa, A + (wr * 64 + i * 16) * ALD5 + kt * 16, ALD5);
                    wmma::mma_sync(fc[i][j], fa, fb, fc[i][j]);
                }
            }
        }
        __syncthreads();
    }

    float* scratch = (float*)hsm5;
#pragma unroll
    for (int i = 0; i < 4; ++i)
#pragma unroll
        for (int j = 0; j < 2; ++j)
            wmma::store_matrix_sync(scratch + (wr * 64 + i * 16) * 132 + wc * 32 + j * 16,
                                    fc[i][j], 132, wmma::mem_row_major);
    __syncthreads();

    for (int i = tid; i < 128 * 128; i += 256) {
        int o = i >> 7, n = i & 127;
        out[((size_t)b * EMB + o0 + o) * NPTS + n0 + n] = fmaxf(scratch[o * 132 + n], 0.f);
    }
}

// ===================== launch =====================
extern "C" void kernel_launch(void* const* d_in, const int* in_sizes, int n_in,
                              void* d_out, int out_size) {
    const float* x  = (const float*)d_in[0];
    const float* w1 = (const float*)d_in[1];
    const float* w2 = (const float*)d_in[2];
    const float* w3 = (const float*)d_in[3];
    const float* w4 = (const float*)d_in[4];
    const float* w5 = (const float*)d_in[5];
    float* out = (float*)d_out;

    const int knn_smem   = NPTS * sizeof(float4);                                   // 64 KB
    const int l1234_smem = (LROWS * HBLD + LROWS * H2LD2 + 2 * WBH) * sizeof(half); // ~101 KB
    const int l5_smem    = 4 * TILEH * sizeof(half);                                // 72 KB
    cudaFuncSetAttribute(knn_kernel,   cudaFuncAttributeMaxDynamicSharedMemorySize, knn_smem);
    cudaFuncSetAttribute(l1234_kernel, cudaFuncAttributeMaxDynamicSharedMemorySize, l1234_smem);
    cudaFuncSetAttribute(l5_kernel,    cudaFuncAttributeMaxDynamicSharedMemorySize, l5_smem);

    wconv_all<<<(W2N + W3N + W4N + W5N) / 1024, 256>>>(w2, w3, w4, w5);
    knn_kernel<<<dim3(NPTS / 16, BATCH), 512, knn_smem>>>(x);
    l1234_kernel<<<(BATCH * NPTS) / LPTS, 256, l1234_smem>>>(x, w1);
    l5_kernel<<<dim3(NPTS / 128, EMB / 128, BATCH), 256, l5_smem>>>(out);
}